// round 16
// baseline (speedup 1.0000x reference)
#include <cuda_runtime.h>
#include <math.h>
#include <stdint.h>

#define NN   50000
#define EE   400000
#define HIDN 128
#define EAK  45
#define OUTK 360
#define NL   3

typedef unsigned long long u64;

// ---- scratch ----
__device__ __align__(16) float g_x   [(size_t)NN * HIDN];
__device__ __align__(16) float g_e   [(size_t)EE * HIDN];
__device__ __align__(16) float g_np  [(size_t)NN * 4 * HIDN];
__device__ __align__(16) float g_agg [(size_t)NN * HIDN];   // kept zero between layers
__device__              float g_deg  [NN];

__device__ __align__(16) float2 g_eWT[23][128];   // edge_W scalar pack (init only)

// tf32 B images: [k(128)][n stride 136].
// 0..2 WeE[l] | 3..5 WpE[l] | 6 W1 | 7..9 W2 chunks | 10..12 WeS[l] | 13..15 WeD[l]
// 16..18 WpS[l] | 19..21 WpD[l] | 22..27 Wpost[l] k-chunks (22+2l+c)
#define IMG_ELEMS 17408     // 128*136
#define N_IMG 28
__device__ __align__(16) uint32_t g_img[N_IMG][IMG_ELEMS];

__device__ __forceinline__ float siluf(float v) {
    return v * (1.0f / (1.0f + __expf(-v)));
}
__device__ __forceinline__ u64 fma2(u64 a, u64 b, u64 c) {
    u64 d;
    asm("fma.rn.f32x2 %0, %1, %2, %3;" : "=l"(d) : "l"(a), "l"(b), "l"(c));
    return d;
}
__device__ __forceinline__ float hadd2(u64 v) {
    float lo, hi;
    asm("mov.b64 {%0, %1}, %2;" : "=f"(lo), "=f"(hi) : "l"(v));
    return lo + hi;
}
__device__ __forceinline__ uint32_t f2t(float v) {
    uint32_t o;
    asm("cvt.rna.tf32.f32 %0, %1;" : "=r"(o) : "f"(v));
    return o;
}

// ===================== warp tf32 MMA =====================
__device__ __forceinline__ void mma1688(float d[4], const uint32_t a[4],
                                        uint32_t b0, uint32_t b1) {
    asm volatile(
        "mma.sync.aligned.m16n8k8.row.col.f32.tf32.tf32.f32 "
        "{%0,%1,%2,%3}, {%4,%5,%6,%7}, {%8,%9}, {%0,%1,%2,%3};\n"
        : "+f"(d[0]), "+f"(d[1]), "+f"(d[2]), "+f"(d[3])
        : "r"(a[0]), "r"(a[1]), "r"(a[2]), "r"(a[3]), "r"(b0), "r"(b1));
}
#define SB_STR 136

// full-width: warp = 16 rows x 64 cols, k=128, B stride 136
__device__ __forceinline__ void gemm16(const uint32_t* __restrict__ sA, int strA,
                                       int kbase, const uint32_t* __restrict__ sB,
                                       int RO, int CO, int lane, float acc[8][4]) {
    int lr = lane >> 2, lc = lane & 3;
#pragma unroll 4
    for (int k = 0; k < 128; k += 8) {
        uint32_t a[4];
        a[0] = sA[(RO + lr)     * strA + kbase + k + lc];
        a[1] = sA[(RO + lr + 8) * strA + kbase + k + lc];
        a[2] = sA[(RO + lr)     * strA + kbase + k + 4 + lc];
        a[3] = sA[(RO + lr + 8) * strA + kbase + k + 4 + lc];
#pragma unroll
        for (int ct = 0; ct < 8; ct++) {
            uint32_t b0 = sB[(k + lc)     * SB_STR + CO + 8 * ct + lr];
            uint32_t b1 = sB[(k + 4 + lc) * SB_STR + CO + 8 * ct + lr];
            mma1688(acc[ct], a, b0, b1);
        }
    }
}
__device__ __forceinline__ void zacc(float acc[8][4]) {
#pragma unroll
    for (int j = 0; j < 8; j++)
#pragma unroll
        for (int q = 0; q < 4; q++) acc[j][q] = 0.0f;
}

// half-width: warp = 16 rows x 32 cols, B half-image stride 72
#define SBH_STR 72
__device__ __forceinline__ void gemm_h(const uint32_t* __restrict__ sA,
                                       const uint32_t* __restrict__ sB,
                                       int RO, int CO32, int lane, float acc[4][4]) {
    int lr = lane >> 2, lc = lane & 3;
#pragma unroll 4
    for (int k = 0; k < 128; k += 8) {
        uint32_t a[4];
        a[0] = sA[(RO + lr)     * 132 + k + lc];
        a[1] = sA[(RO + lr + 8) * 132 + k + lc];
        a[2] = sA[(RO + lr)     * 132 + k + 4 + lc];
        a[3] = sA[(RO + lr + 8) * 132 + k + 4 + lc];
#pragma unroll
        for (int ct = 0; ct < 4; ct++) {
            uint32_t b0 = sB[(k + lc)     * SBH_STR + CO32 + 8 * ct + lr];
            uint32_t b1 = sB[(k + 4 + lc) * SBH_STR + CO32 + 8 * ct + lr];
            mma1688(acc[ct], a, b0, b1);
        }
    }
}
__device__ __forceinline__ void zacc4(float acc[4][4]) {
#pragma unroll
    for (int j = 0; j < 4; j++)
#pragma unroll
        for (int q = 0; q < 4; q++) acc[j][q] = 0.0f;
}

// stage fragment accumulators into a [64][stride] f32 smem tile
__device__ __forceinline__ void stage_acc(float* st, int str, int RO, int CO,
                                          int lane, const float acc[8][4]) {
    int lr = lane >> 2, lc2 = (lane & 3) * 2;
    int r0 = RO + lr, r1 = r0 + 8;
#pragma unroll
    for (int ct = 0; ct < 8; ct++) {
        int c = CO + 8 * ct + lc2;
        *(float2*)(st + r0 * str + c) = make_float2(acc[ct][0], acc[ct][1]);
        *(float2*)(st + r1 * str + c) = make_float2(acc[ct][2], acc[ct][3]);
    }
}
__device__ __forceinline__ void stage_h(float* st, int RO, int cbase,
                                        int lane, const float acc[4][4]) {
    int lr = lane >> 2, lc2 = (lane & 3) * 2;
    int r0 = RO + lr, r1 = r0 + 8;
#pragma unroll
    for (int ct = 0; ct < 4; ct++) {
        int c = cbase + 8 * ct + lc2;
        *(float2*)(st + r0 * 132 + c) = make_float2(acc[ct][0], acc[ct][1]);
        *(float2*)(st + r1 * 132 + c) = make_float2(acc[ct][2], acc[ct][3]);
    }
}

// ---------------------------------------------------------------------------
__global__ void k_pack_all(const float* __restrict__ We, const float* __restrict__ Wp,
                           const float* __restrict__ Wpo, const float* __restrict__ W1,
                           const float* __restrict__ W2, const float* __restrict__ eW,
                           int Ntot) {
    int i = blockIdx.x * blockDim.x + threadIdx.x;
    if (i < 2944) {
        int j = i % 128, p = i / 128;
        float a = eW[(size_t)j * EAK + 2 * p];
        float b = (2 * p + 1 < EAK) ? eW[(size_t)j * EAK + 2 * p + 1] : 0.0f;
        g_eWT[p][j] = make_float2(a, b);
        return;
    }
    i -= 2944;
    if (i < N_IMG * IMG_ELEMS) {
        int t = i / IMG_ELEMS, r = i % IMG_ELEMS, k = r / SB_STR, n = r % SB_STR;
        float v = 0.0f;
        if (n < 128) {
            if (t < 3)        v = We[(size_t)t * 49152 + (size_t)n * 384 + 256 + k];
            else if (t < 6)   v = Wp[(size_t)(t - 3) * 49152 + (size_t)n * 384 + 256 + k];
            else if (t == 6)  v = W1[(size_t)n * 128 + k];
            else if (t < 10)  { int o = (t - 7) * 128 + n; if (o < OUTK) v = W2[(size_t)o * 128 + k]; }
            else if (t < 13)  v = We[(size_t)(t - 10) * 49152 + (size_t)n * 384 + k];
            else if (t < 16)  v = We[(size_t)(t - 13) * 49152 + (size_t)n * 384 + 128 + k];
            else if (t < 19)  v = Wp[(size_t)(t - 16) * 49152 + (size_t)n * 384 + k];
            else if (t < 22)  v = Wp[(size_t)(t - 19) * 49152 + (size_t)n * 384 + 128 + k];
            else {
                int l = (t - 22) >> 1, c = (t - 22) & 1;
                v = Wpo[(size_t)l * 32768 + (size_t)n * 256 + 128 * c + k];
            }
        }
        ((uint32_t*)g_img)[i] = f2t(v);
        return;
    }
    i -= N_IMG * IMG_ELEMS;
    if (i < Ntot) g_deg[i] = 0.0f;
}

__global__ void k_count_deg(const int* __restrict__ ei, int Etot) {
    int i = blockIdx.x * blockDim.x + threadIdx.x;
    if (i < Etot) atomicAdd(&g_deg[ei[Etot + i]], 1.0f);
}

// ---------------------------------------------------------------------------
// fused init: blocks [0,N) node_init, blocks [N, N+ceil(E/16)) edge_init
__global__ void __launch_bounds__(128) k_init_fused(
        const float* __restrict__ pos, const int* __restrict__ pos_w,
        const float* __restrict__ wte, const float* __restrict__ nW,
        const float* __restrict__ nb,
        const float* __restrict__ ea, const int* __restrict__ et,
        const float* __restrict__ lemb, const float* __restrict__ eb,
        int Ntot, int Etot) {
    int j = threadIdx.x;
    if ((int)blockIdx.x < Ntot) {
        int n = blockIdx.x;
        __shared__ float s_pos[8];
        if (j < 8) s_pos[j] = pos[(size_t)n * 8 + j];
        __syncthreads();
        float acc = nb[j] + wte[(size_t)pos_w[n] * HIDN + j];
#pragma unroll
        for (int k = 0; k < 8; k++) acc += s_pos[k] * nW[j * 8 + k];
        g_x[(size_t)n * HIDN + j] = acc;
        return;
    }
    int e0 = (blockIdx.x - Ntot) * 16;
    __shared__ __align__(16) float s_a[16][46];
    __shared__ int s_t[16];
    int nv = min(16, Etot - e0);
    for (int idx = j; idx < nv * EAK; idx += 128) {
        int t = idx / EAK, k = idx % EAK;
        s_a[t][k] = ea[(size_t)(e0 + t) * EAK + k];
    }
    if (j < 16) { s_a[j][45] = 0.0f; s_t[j] = (j < nv) ? et[e0 + j] : 0; }
    __syncthreads();
    u64 acc[16];
#pragma unroll
    for (int t = 0; t < 16; t++) acc[t] = 0ull;
    const u64* wp = (const u64*)&g_eWT[0][0];
#pragma unroll
    for (int p = 0; p < 23; p++) {
        u64 w = wp[p * 128 + j];
#pragma unroll
        for (int t = 0; t < 16; t++)
            acc[t] = fma2(*(const u64*)&s_a[t][2 * p], w, acc[t]);
    }
    float ebj = eb[j];
    for (int t = 0; t < nv; t++)
        g_e[(size_t)(e0 + t) * HIDN + j] =
            lemb[(size_t)s_t[t] * HIDN + j] + hadd2(acc[t]) + ebj;
}

// ---------------------------------------------------------------------------
// TENSOR node_pre: 64 nodes/CTA, 4 GEMMs -> g_np
#define NP_STR  132
#define NP_SMEM ((64 * NP_STR + IMG_ELEMS) * 4)
__global__ void __launch_bounds__(256, 2) k_node_pre_m(int l, int Ntot) {
    extern __shared__ float sm[];
    uint32_t* sA = (uint32_t*)sm;
    uint32_t* sB = (uint32_t*)sm + 64 * NP_STR;
    int tid = threadIdx.x, lane = tid & 31, w = tid >> 5;
    int RO = (w >> 1) * 16, CO = (w & 1) * 64;
    int n0 = blockIdx.x * 64;
    int nv = min(64, Ntot - n0);

    const float4* src = (const float4*)(g_x + (size_t)n0 * HIDN);
    for (int i = tid; i < 2048; i += 256) {
        int r = i >> 5, k = (i & 31) << 2;
        uint4 t4 = make_uint4(0u, 0u, 0u, 0u);
        if (r < nv) {
            float4 v = src[i];
            t4 = make_uint4(f2t(v.x), f2t(v.y), f2t(v.z), f2t(v.w));
        }
        *(uint4*)&sA[r * NP_STR + k] = t4;
    }

    int lr = lane >> 2, lc2 = (lane & 3) * 2;
    const int imgs[4] = { 10 + l, 13 + l, 16 + l, 19 + l };
#pragma unroll 1
    for (int blk = 0; blk < 4; blk++) {
        const uint4* ws = (const uint4*)&g_img[imgs[blk]][0];
        uint4* wd = (uint4*)sB;
        for (int i = tid; i < IMG_ELEMS / 4; i += 256) wd[i] = ws[i];
        __syncthreads();
        float acc[8][4];
        zacc(acc);
        gemm16(sA, NP_STR, 0, sB, RO, CO, lane, acc);
        int r0 = RO + lr, r1 = r0 + 8;
#pragma unroll
        for (int ct = 0; ct < 8; ct++) {
            int c = blk * 128 + CO + 8 * ct + lc2;
            if (r0 < nv) *(float2*)&g_np[(size_t)(n0 + r0) * 512 + c] =
                make_float2(acc[ct][0], acc[ct][1]);
            if (r1 < nv) *(float2*)&g_np[(size_t)(n0 + r1) * 512 + c] =
                make_float2(acc[ct][2], acc[ct][3]);
        }
        __syncthreads();
    }
}

// ---------------------------------------------------------------------------
// TENSOR edge layer: 64 edges/CTA, 3 CTAs/SM via half-width B streaming.
// smem floats: A 8448 | Bhalf 9216 | b1 128 | b2 128 | src 64 | dst 64
#define EL_A    0
#define EL_B    8448
#define EL_B1   (EL_B + 128 * SBH_STR)   // 17664
#define EL_B2   (EL_B1 + 128)
#define EL_SRC  (EL_B2 + 128)
#define EL_DST  (EL_SRC + 64)
#define EL_SMEM ((EL_DST + 64) * 4)      // 72192 B -> 3 CTAs/SM

// copy half h (64 cols) of image t into sB (stride 72)
__device__ __forceinline__ void copy_bhalf(uint32_t* sB, int t, int h, int tid) {
    const uint4* ws = (const uint4*)&g_img[t][0];
    uint4* wd = (uint4*)sB;
#pragma unroll 4
    for (int i = tid; i < 2048; i += 256) {
        int k = i >> 4, q = i & 15;
        wd[k * (SBH_STR / 4) + q] = ws[k * 34 + 16 * h + q];
    }
}

__global__ void __launch_bounds__(256, 3) k_edge_layer_m(
        const int* __restrict__ ei, const float* __restrict__ be,
        const float* __restrict__ bpre, int l, int Etot) {
    extern __shared__ float sm[];
    uint32_t* sA = (uint32_t*)(sm + EL_A);
    float*    fA = sm + EL_A;
    uint32_t* sB = (uint32_t*)(sm + EL_B);
    float* sb1 = sm + EL_B1;
    float* sb2 = sm + EL_B2;
    int* ssrc = (int*)(sm + EL_SRC);
    int* sdst = (int*)(sm + EL_DST);

    int tid = threadIdx.x, lane = tid & 31, w = tid >> 5;
    int RO = (w >> 1) * 16, CO32 = (w & 1) * 32;
    int e0 = blockIdx.x * 64;
    int nv = min(64, Etot - e0);

    if (tid < 128) { sb1[tid] = be[tid]; sb2[tid] = bpre[tid]; }
    else if (tid < 192) {
        int t = tid - 128, valid = t < nv;
        ssrc[t] = valid ? ei[e0 + t] : 0;
        sdst[t] = valid ? ei[Etot + e0 + t] : 0;
    }
    {
        const float4* src = (const float4*)(g_e + (size_t)e0 * HIDN);
        for (int i = tid; i < 2048; i += 256) {
            int r = i >> 5, k = (i & 31) << 2;
            uint4 t4 = make_uint4(0u, 0u, 0u, 0u);
            if (r < nv) {
                float4 v = src[i];
                t4 = make_uint4(f2t(v.x), f2t(v.y), f2t(v.z), f2t(v.w));
            }
            *(uint4*)&sA[r * 132 + k] = t4;
        }
    }

    int k0 = lane * 4;
    float accA[4][4], accB[4][4];

    // ============ phase 1: e' = silu(e@WeE + be + a1[src] + a2[dst]) =======
    copy_bhalf(sB, l, 0, tid);
    __syncthreads();
    zacc4(accA);
    gemm_h(sA, sB, RO, CO32, lane, accA);
    __syncthreads();
    copy_bhalf(sB, l, 1, tid);
    __syncthreads();
    zacc4(accB);
    gemm_h(sA, sB, RO, CO32, lane, accB);
    __syncthreads();                     // all sA reads done

    stage_h(fA, RO, CO32,      lane, accA);   // cols [CO32, CO32+32)
    stage_h(fA, RO, 64 + CO32, lane, accB);   // cols [64+CO32, ...)
    __syncthreads();

    // epilogue 1 (row-per-warp, in-place in sA)
    {
        float4 bb = *(const float4*)(sb1 + k0);
#pragma unroll 2
        for (int rr = 0; rr < 8; rr++) {
            int r = w * 8 + rr;
            int sn = ssrc[r], dn = sdst[r];
            float4 a = *(const float4*)(fA + r * 132 + k0);
            float4 p = *(const float4*)(g_np + (size_t)sn * 512 + k0);
            float4 q = *(const float4*)(g_np + (size_t)dn * 512 + 128 + k0);
            float v0 = siluf(a.x + bb.x + p.x + q.x);
            float v1 = siluf(a.y + bb.y + p.y + q.y);
            float v2 = siluf(a.z + bb.z + p.z + q.z);
            float v3 = siluf(a.w + bb.w + p.w + q.w);
            if (r < nv)
                *(float4*)(g_e + (size_t)(e0 + r) * HIDN + k0) =
                    make_float4(v0, v1, v2, v3);
            *(uint4*)(sA + r * 132 + k0) =
                make_uint4(f2t(v0), f2t(v1), f2t(v2), f2t(v3));
        }
    }
    __syncthreads();

    // ============ phase 2: m = silu(e'@WpE + bpre + p1[src] + p2[dst]) =====
    copy_bhalf(sB, 3 + l, 0, tid);
    __syncthreads();
    zacc4(accA);
    gemm_h(sA, sB, RO, CO32, lane, accA);
    __syncthreads();
    copy_bhalf(sB, 3 + l, 1, tid);
    __syncthreads();
    zacc4(accB);
    gemm_h(sA, sB, RO, CO32, lane, accB);
    __syncthreads();

    stage_h(fA, RO, CO32,      lane, accA);
    stage_h(fA, RO, 64 + CO32, lane, accB);
    __syncthreads();

    // epilogue 2 (row-per-warp): agg[dst] += m
    {
        float4 bb = *(const float4*)(sb2 + k0);
#pragma unroll 2
        for (int rr = 0; rr < 8; rr++) {
            int r = w * 8 + rr;
            if (r >= nv) break;
            int sn = ssrc[r], dn = sdst[r];
            float4 a = *(const float4*)(fA + r * 132 + k0);
            float4 p = *(const float4*)(g_np + (size_t)sn * 512 + 256 + k0);
            float4 q = *(const float4*)(g_np + (size_t)dn * 512 + 384 + k0);
            float m0 = siluf(a.x + bb.x + p.x + q.x);
            float m1 = siluf(a.y + bb.y + p.y + q.y);
            float m2 = siluf(a.z + bb.z + p.z + q.z);
            float m3 = siluf(a.w + bb.w + p.w + q.w);
            asm volatile("red.add.v4.f32 [%0], {%1, %2, %3, %4};"
                         :: "l"(g_agg + (size_t)dn * HIDN + k0),
                            "f"(m0), "f"(m1), "f"(m2), "f"(m3) : "memory");
        }
    }
}

// ---------------------------------------------------------------------------
// TENSOR node_post: 32 nodes/CTA, 128 threads; K=256 via 2 accumulating chunks
#define PO_STR  264
#define PO_B    (32 * PO_STR)            // 8448
#define PO_BIA  (PO_B + IMG_ELEMS)       // 25856
#define PO_INV  (PO_BIA + 128)
#define PO_SMEM ((PO_INV + 32) * 4)
__global__ void __launch_bounds__(128, 2) k_node_post_m(
        const float* __restrict__ bpost, int l, int do_silu, int Ntot) {
    extern __shared__ float sm[];
    uint32_t* sA = (uint32_t*)sm;
    uint32_t* sB = (uint32_t*)sm + PO_B;
    float* sbias = sm + PO_BIA;
    float* sinv  = sm + PO_INV;

    int tid = threadIdx.x, lane = tid & 31, w = tid >> 5;
    int RO = (w >> 1) * 16, CO = (w & 1) * 64;
    int n0 = blockIdx.x * 32;
    int nv = min(32, Ntot - n0);

    if (tid < 128) sbias[tid] = bpost[tid];
    if (tid < 32) sinv[tid] = (tid < nv) ? 1.0f / fmaxf(g_deg[n0 + tid], 1.0f) : 0.0f;
    __syncthreads();

    for (int i = tid; i < 2048; i += 128) {
        int r = i >> 6, k = (i & 63) << 2;
        uint4 t4 = make_uint4(0u, 0u, 0u, 0u);
        if (r < nv) {
            if (k < 128) {
                float4 v = *(const float4*)(g_x + (size_t)(n0 + r) * HIDN + k);
                t4 = make_uint4(f2t(v.x), f2t(v.y), f2t(v.z), f2t(v.w));
            } else {
                float inv = sinv[r];
                float* ap = g_agg + (size_t)(n0 + r) * HIDN + (k - 128);
                float4 v = *(const float4*)ap;
                t4 = make_uint4(f2t(v.x * inv), f2t(v.y * inv), f2t(v.z * inv), f2t(v.w * inv));
                *(float4*)ap = make_float4(0.f, 0.f, 0.f, 0.f);  // re-zero for next layer
            }
        }
        *(uint4*)&sA[r * PO_STR + k] = t4;
    }

    float acc[8][4];
    zacc(acc);
#pragma unroll 1
    for (int cchunk = 0; cchunk < 2; cchunk++) {
        const uint4* ws = (const uint4*)&g_img[22 + 2 * l + cchunk][0];
        uint4* wd = (uint4*)sB;
        for (int i = tid; i < IMG_ELEMS / 4; i += 128) wd[i] = ws[i];
        __syncthreads();
        gemm16(sA, PO_STR, cchunk * 128, sB, RO, CO, lane, acc);
        __syncthreads();
    }

    int lr = lane >> 2, lc2 = (lane & 3) * 2;
    int r0 = RO + lr, r1 = r0 + 8;
#pragma unroll
    for (int ct = 0; ct < 8; ct++) {
        int c = CO + 8 * ct + lc2;
        float b0v = sbias[c], b1v = sbias[c + 1];
        float v00 = acc[ct][0] + b0v, v01 = acc[ct][1] + b1v;
        float v10 = acc[ct][2] + b0v, v11 = acc[ct][3] + b1v;
        if (do_silu) { v00 = siluf(v00); v01 = siluf(v01); v10 = siluf(v10); v11 = siluf(v11); }
        if (r0 < nv) *(float2*)&g_x[(size_t)(n0 + r0) * HIDN + c] = make_float2(v00, v01);
        if (r1 < nv) *(float2*)&g_x[(size_t)(n0 + r1) * HIDN + c] = make_float2(v10, v11);
    }
}

__global__ void k_copy_x(float* __restrict__ out, int Ntot) {
    int i = blockIdx.x * blockDim.x + threadIdx.x;
    if (i < Ntot * HIDN) out[i] = g_x[i];
}

// ---------------------------------------------------------------------------
// TENSOR readout: 64 edges/CTA, row-major staged epilogues
#define RD_A    0
#define RD_B    (64 * 132)
#define RD_B1   (RD_B + IMG_ELEMS)       // 25856
#define RD_B2   (RD_B1 + 128)
#define RD_RES  (RD_B2 + 384)
#define RD_SMEM ((RD_RES + 64 * 12) * 4)

__global__ void __launch_bounds__(256, 2) k_readout_m(
        const float* __restrict__ ea, const float* __restrict__ b1,
        const float* __restrict__ b2, float* __restrict__ out, int Etot) {
    extern __shared__ float sm[];
    uint32_t* sA = (uint32_t*)(sm + RD_A);
    uint32_t* sB = (uint32_t*)(sm + RD_B);
    float*    fB = sm + RD_B;            // staging view of sB
    float* sb1 = sm + RD_B1;
    float* sb2 = sm + RD_B2;
    float* sres = sm + RD_RES;      // [64 rows][12] (9 used)

    int tid = threadIdx.x, lane = tid & 31, w = tid >> 5;
    int RO = (w >> 1) * 16, CO = (w & 1) * 64;
    int e0 = blockIdx.x * 64;
    int nv = min(64, Etot - e0);

    if (tid < 128) sb1[tid] = b1[tid];
    for (int i = tid; i < 384; i += 256) sb2[i] = (i < OUTK) ? b2[i] : 0.0f;
    for (int i = tid; i < 64 * 9; i += 256) {
        int r = i / 9, m = i % 9;
        sres[r * 12 + m] = (r < nv) ? ea[(size_t)(e0 + r) * EAK + m * 5 + 4] : 0.0f;
    }
    {
        const float4* src = (const float4*)(g_e + (size_t)e0 * HIDN);
        for (int i = tid; i < 2048; i += 256) {
            int r = i >> 5, k = (i & 31) << 2;
            uint4 t4 = make_uint4(0u, 0u, 0u, 0u);
            if (r < nv) {
                float4 v = src[i];
                t4 = make_uint4(f2t(v.x), f2t(v.y), f2t(v.z), f2t(v.w));
            }
            *(uint4*)&sA[r * 132 + k] = t4;
        }
        const uint4* ws = (const uint4*)&g_img[6][0];
        uint4* wd = (uint4*)sB;
        for (int i = tid; i < IMG_ELEMS / 4; i += 256) wd[i] = ws[i];
    }
    __syncthreads();

    float acc[8][4];
    zacc(acc);
    gemm16(sA, 132, 0, sB, RO, CO, lane, acc);
    __syncthreads();                     // done reading sA & sB

    stage_acc(fB, 132, RO, CO, lane, acc);
    __syncthreads();

    // h = silu(D + b1) -> sA (tf32), row-per-warp
    int k0 = lane * 4;
    {
        float4 bb = *(const float4*)(sb1 + k0);
#pragma unroll 2
        for (int rr = 0; rr < 8; rr++) {
            int r = w * 8 + rr;
            float4 a = *(const float4*)(fB + r * 132 + k0);
            *(uint4*)(sA + r * 132 + k0) = make_uint4(
                f2t(siluf(a.x + bb.x)), f2t(siluf(a.y + bb.y)),
                f2t(siluf(a.z + bb.z)), f2t(siluf(a.w + bb.w)));
        }
    }
    __syncthreads();

#pragma unroll 1
    for (int cc = 0; cc < 3; cc++) {
        const uint4* ws = (const uint4*)&g_img[7 + cc][0];
        uint4* wd = (uint4*)sB;
        for (int i = tid; i < IMG_ELEMS / 4; i += 256) wd[i] = ws[i];
        __syncthreads();
        zacc(acc);
        gemm16(sA, 132, 0, sB, RO, CO, lane, acc);
        __syncthreads();                 // done reading sB (and sA)

        stage_acc(fB, 132, RO, CO, lane, acc);
        __syncthreads();

        int o = cc * 128 + k0;
        if (o < OUTK) {                  // 4-block never straddles 40-boundary
            int mf = o / 40;
            float4 bb = *(const float4*)(sb2 + o);
#pragma unroll 2
            for (int rr = 0; rr < 8; rr++) {
                int r = w * 8 + rr;
                if (r >= nv) break;
                float4 a = *(const float4*)(fB + r * 132 + k0);
                float rv = sres[r * 12 + mf];
                *(float4*)(out + (size_t)(e0 + r) * OUTK + o) =
                    make_float4(a.x + bb.x + rv, a.y + bb.y + rv,
                                a.z + bb.z + rv, a.w + bb.w + rv);
            }
        }
        __syncthreads();                 // staging reads done before next copy
    }
}

// ===========================================================================
extern "C" void kernel_launch(void* const* d_in, const int* in_sizes, int n_in,
                              void* d_out, int out_size) {
    const float* edge_attr   = (const float*)d_in[0];
    const int*   edge_type   = (const int*)  d_in[1];
    const float* pos         = (const float*)d_in[2];
    const int*   pos_w       = (const int*)  d_in[3];
    const int*   edge_index  = (const int*)  d_in[4];
    const float* layer_embed = (const float*)d_in[5];
    const float* wte         = (const float*)d_in[6];
    const float* node_W      = (const float*)d_in[7];
    const float* node_b      = (const float*)d_in[8];
    const float* edge_W      = (const float*)d_in[9];
    const float* edge_b      = (const float*)d_in[10];
    const float* gnn_We      = (const float*)d_in[11];
    const float* gnn_be      = (const float*)d_in[12];
    const float* gnn_Wpre    = (const float*)d_in[13];
    const float* gnn_bpre    = (const float*)d_in[14];
    const float* gnn_Wpost   = (const float*)d_in[15];
    const float* gnn_bpost   = (const float*)d_in[16];
    const float* out_W1      = (const float*)d_in[17];
    const float* out_b1      = (const float*)d_in[18];
    const float* out_W2      = (const float*)d_in[19];
    const float* out_b2      = (const float*)d_in[20];

    int E = in_sizes[1];
    int N = in_sizes[3];
    if (E > EE) E = EE;
    if (N > NN) N = NN;

    float* outp = (float*)d_out;
    float* out_x = nullptr; float* out_o = nullptr;
    long xsz = (long)N * HIDN, osz = (long)E * OUTK;
    if ((long)out_size >= xsz + osz)      { out_x = outp; out_o = outp + xsz; }
    else if ((long)out_size == osz)       { out_o = outp; }
    else                                  { out_x = outp; }

    cudaFuncSetAttribute(k_edge_layer_m, cudaFuncAttributeMaxDynamicSharedMemorySize, EL_SMEM);
    cudaFuncSetAttribute(k_readout_m,    cudaFuncAttributeMaxDynamicSharedMemorySize, RD_SMEM);
    cudaFuncSetAttribute(k_node_pre_m,   cudaFuncAttributeMaxDynamicSharedMemorySize, NP_SMEM);
    cudaFuncSetAttribute(k_node_post_m,  cudaFuncAttributeMaxDynamicSharedMemorySize, PO_SMEM);

    int EB16 = (E + 15) / 16;
    int EB64 = (E + 63) / 64, NB64 = (N + 63) / 64, NB32 = (N + 31) / 32;
    int packN = 2944 + N_IMG * IMG_ELEMS + N;

    k_pack_all<<<(packN + 255) / 256, 256>>>(gnn_We, gnn_Wpre, gnn_Wpost,
                                             out_W1, out_W2, edge_W, N);          // 1
    k_init_fused<<<N + EB16, 128>>>(pos, pos_w, wte, node_W, node_b,
                                    edge_attr, edge_type, layer_embed, edge_b,
                                    N, E);                                        // 2
    k_node_pre_m<<<NB64, 256, NP_SMEM>>>(0, N);                                   // 3
    k_edge_layer_m<<<EB64, 256, EL_SMEM>>>(edge_index, gnn_be, gnn_bpre, 0, E);   // 4 (profiled)
    k_count_deg<<<(E + 255) / 256, 256>>>(edge_index, E);                         // 5
    k_node_post_m<<<NB32, 128, PO_SMEM>>>(gnn_bpost, 0, 1, N);                    // 6

    for (int l = 1; l < NL; l++) {
        k_node_pre_m<<<NB64, 256, NP_SMEM>>>(l, N);
        k_edge_layer_m<<<EB64, 256, EL_SMEM>>>(edge_index,
                                               gnn_be + l * HIDN,
                                               gnn_bpre + l * HIDN, l, E);
        k_node_post_m<<<NB32, 128, PO_SMEM>>>(gnn_bpost + l * HIDN, l,
                                              (l < NL - 1) ? 1 : 0, N);
    }

    if (out_x) k_copy_x<<<((long)N * HIDN + 255) / 256, 256>>>(out_x, N);
    if (out_o) k_readout_m<<<EB64, 256, RD_SMEM>>>(edge_attr, out_b1, out_b2, out_o, E);
}

// round 17
// speedup vs baseline: 1.0067x; 1.0067x over previous
#include <cuda_runtime.h>
#include <math.h>
#include <stdint.h>

#define NN   50000
#define EE   400000
#define HIDN 128
#define EAK  45
#define OUTK 360
#define NL   3

typedef unsigned long long u64;

// ---- scratch ----
__device__ __align__(16) float g_x   [(size_t)NN * HIDN];
__device__ __align__(16) float g_e   [(size_t)EE * HIDN];
__device__ __align__(16) float g_np  [(size_t)NN * 4 * HIDN];
__device__ __align__(16) float g_agg [(size_t)NN * HIDN];   // kept zero between layers
__device__              float g_deg  [NN];

__device__ __align__(16) float2 g_eWT[23][128];   // edge_W scalar pack (init only)

// tf32 B images: [k(128)][n stride 136].
// 0..2 WeE[l] | 3..5 WpE[l] | 6 W1 | 7..9 W2 chunks | 10..12 WeS[l] | 13..15 WeD[l]
// 16..18 WpS[l] | 19..21 WpD[l] | 22..27 Wpost[l] k-chunks (22+2l+c)
#define IMG_ELEMS 17408     // 128*136
#define N_IMG 28
__device__ __align__(16) uint32_t g_img[N_IMG][IMG_ELEMS];

__device__ __forceinline__ float siluf(float v) {
    return v * (1.0f / (1.0f + __expf(-v)));
}
__device__ __forceinline__ u64 fma2(u64 a, u64 b, u64 c) {
    u64 d;
    asm("fma.rn.f32x2 %0, %1, %2, %3;" : "=l"(d) : "l"(a), "l"(b), "l"(c));
    return d;
}
__device__ __forceinline__ float hadd2(u64 v) {
    float lo, hi;
    asm("mov.b64 {%0, %1}, %2;" : "=f"(lo), "=f"(hi) : "l"(v));
    return lo + hi;
}
__device__ __forceinline__ uint32_t f2t(float v) {
    uint32_t o;
    asm("cvt.rna.tf32.f32 %0, %1;" : "=r"(o) : "f"(v));
    return o;
}

// ===================== warp tf32 MMA =====================
__device__ __forceinline__ void mma1688(float d[4], const uint32_t a[4],
                                        uint32_t b0, uint32_t b1) {
    asm volatile(
        "mma.sync.aligned.m16n8k8.row.col.f32.tf32.tf32.f32 "
        "{%0,%1,%2,%3}, {%4,%5,%6,%7}, {%8,%9}, {%0,%1,%2,%3};\n"
        : "+f"(d[0]), "+f"(d[1]), "+f"(d[2]), "+f"(d[3])
        : "r"(a[0]), "r"(a[1]), "r"(a[2]), "r"(a[3]), "r"(b0), "r"(b1));
}
#define SB_STR 136

// full-width: warp = 16 rows x 64 cols, k=128, B stride 136
__device__ __forceinline__ void gemm16(const uint32_t* __restrict__ sA, int strA,
                                       int kbase, const uint32_t* __restrict__ sB,
                                       int RO, int CO, int lane, float acc[8][4]) {
    int lr = lane >> 2, lc = lane & 3;
#pragma unroll 4
    for (int k = 0; k < 128; k += 8) {
        uint32_t a[4];
        a[0] = sA[(RO + lr)     * strA + kbase + k + lc];
        a[1] = sA[(RO + lr + 8) * strA + kbase + k + lc];
        a[2] = sA[(RO + lr)     * strA + kbase + k + 4 + lc];
        a[3] = sA[(RO + lr + 8) * strA + kbase + k + 4 + lc];
#pragma unroll
        for (int ct = 0; ct < 8; ct++) {
            uint32_t b0 = sB[(k + lc)     * SB_STR + CO + 8 * ct + lr];
            uint32_t b1 = sB[(k + 4 + lc) * SB_STR + CO + 8 * ct + lr];
            mma1688(acc[ct], a, b0, b1);
        }
    }
}
__device__ __forceinline__ void zacc(float acc[8][4]) {
#pragma unroll
    for (int j = 0; j < 8; j++)
#pragma unroll
        for (int q = 0; q < 4; q++) acc[j][q] = 0.0f;
}

// half-width: warp = 16 rows x 32 cols, B half-image stride 72
#define SBH_STR 72
__device__ __forceinline__ void gemm_h(const uint32_t* __restrict__ sA,
                                       const uint32_t* __restrict__ sB,
                                       int RO, int CO32, int lane, float acc[4][4]) {
    int lr = lane >> 2, lc = lane & 3;
#pragma unroll 4
    for (int k = 0; k < 128; k += 8) {
        uint32_t a[4];
        a[0] = sA[(RO + lr)     * 132 + k + lc];
        a[1] = sA[(RO + lr + 8) * 132 + k + lc];
        a[2] = sA[(RO + lr)     * 132 + k + 4 + lc];
        a[3] = sA[(RO + lr + 8) * 132 + k + 4 + lc];
#pragma unroll
        for (int ct = 0; ct < 4; ct++) {
            uint32_t b0 = sB[(k + lc)     * SBH_STR + CO32 + 8 * ct + lr];
            uint32_t b1 = sB[(k + 4 + lc) * SBH_STR + CO32 + 8 * ct + lr];
            mma1688(acc[ct], a, b0, b1);
        }
    }
}
__device__ __forceinline__ void zacc4(float acc[4][4]) {
#pragma unroll
    for (int j = 0; j < 4; j++)
#pragma unroll
        for (int q = 0; q < 4; q++) acc[j][q] = 0.0f;
}

// stage fragment accumulators into a [64][stride] f32 smem tile
__device__ __forceinline__ void stage_acc(float* st, int str, int RO, int CO,
                                          int lane, const float acc[8][4]) {
    int lr = lane >> 2, lc2 = (lane & 3) * 2;
    int r0 = RO + lr, r1 = r0 + 8;
#pragma unroll
    for (int ct = 0; ct < 8; ct++) {
        int c = CO + 8 * ct + lc2;
        *(float2*)(st + r0 * str + c) = make_float2(acc[ct][0], acc[ct][1]);
        *(float2*)(st + r1 * str + c) = make_float2(acc[ct][2], acc[ct][3]);
    }
}
__device__ __forceinline__ void stage_h(float* st, int RO, int cbase,
                                        int lane, const float acc[4][4]) {
    int lr = lane >> 2, lc2 = (lane & 3) * 2;
    int r0 = RO + lr, r1 = r0 + 8;
#pragma unroll
    for (int ct = 0; ct < 4; ct++) {
        int c = cbase + 8 * ct + lc2;
        *(float2*)(st + r0 * 132 + c) = make_float2(acc[ct][0], acc[ct][1]);
        *(float2*)(st + r1 * 132 + c) = make_float2(acc[ct][2], acc[ct][3]);
    }
}

// ---------------------------------------------------------------------------
__global__ void k_pack_all(const float* __restrict__ We, const float* __restrict__ Wp,
                           const float* __restrict__ Wpo, const float* __restrict__ W1,
                           const float* __restrict__ W2, const float* __restrict__ eW,
                           int Ntot) {
    int i = blockIdx.x * blockDim.x + threadIdx.x;
    if (i < 2944) {
        int j = i % 128, p = i / 128;
        float a = eW[(size_t)j * EAK + 2 * p];
        float b = (2 * p + 1 < EAK) ? eW[(size_t)j * EAK + 2 * p + 1] : 0.0f;
        g_eWT[p][j] = make_float2(a, b);
        return;
    }
    i -= 2944;
    if (i < N_IMG * IMG_ELEMS) {
        int t = i / IMG_ELEMS, r = i % IMG_ELEMS, k = r / SB_STR, n = r % SB_STR;
        float v = 0.0f;
        if (n < 128) {
            if (t < 3)        v = We[(size_t)t * 49152 + (size_t)n * 384 + 256 + k];
            else if (t < 6)   v = Wp[(size_t)(t - 3) * 49152 + (size_t)n * 384 + 256 + k];
            else if (t == 6)  v = W1[(size_t)n * 128 + k];
            else if (t < 10)  { int o = (t - 7) * 128 + n; if (o < OUTK) v = W2[(size_t)o * 128 + k]; }
            else if (t < 13)  v = We[(size_t)(t - 10) * 49152 + (size_t)n * 384 + k];
            else if (t < 16)  v = We[(size_t)(t - 13) * 49152 + (size_t)n * 384 + 128 + k];
            else if (t < 19)  v = Wp[(size_t)(t - 16) * 49152 + (size_t)n * 384 + k];
            else if (t < 22)  v = Wp[(size_t)(t - 19) * 49152 + (size_t)n * 384 + 128 + k];
            else {
                int l = (t - 22) >> 1, c = (t - 22) & 1;
                v = Wpo[(size_t)l * 32768 + (size_t)n * 256 + 128 * c + k];
            }
        }
        ((uint32_t*)g_img)[i] = f2t(v);
        return;
    }
    i -= N_IMG * IMG_ELEMS;
    if (i < Ntot) g_deg[i] = 0.0f;
}

__global__ void k_count_deg(const int* __restrict__ ei, int Etot) {
    int i = blockIdx.x * blockDim.x + threadIdx.x;
    if (i < Etot) atomicAdd(&g_deg[ei[Etot + i]], 1.0f);
}

// ---------------------------------------------------------------------------
// fused init: blocks [0,N) node_init, blocks [N, N+ceil(E/16)) edge_init
__global__ void __launch_bounds__(128) k_init_fused(
        const float* __restrict__ pos, const int* __restrict__ pos_w,
        const float* __restrict__ wte, const float* __restrict__ nW,
        const float* __restrict__ nb,
        const float* __restrict__ ea, const int* __restrict__ et,
        const float* __restrict__ lemb, const float* __restrict__ eb,
        int Ntot, int Etot) {
    int j = threadIdx.x;
    if ((int)blockIdx.x < Ntot) {
        int n = blockIdx.x;
        __shared__ float s_pos[8];
        if (j < 8) s_pos[j] = pos[(size_t)n * 8 + j];
        __syncthreads();
        float acc = nb[j] + wte[(size_t)pos_w[n] * HIDN + j];
#pragma unroll
        for (int k = 0; k < 8; k++) acc += s_pos[k] * nW[j * 8 + k];
        g_x[(size_t)n * HIDN + j] = acc;
        return;
    }
    int e0 = (blockIdx.x - Ntot) * 16;
    __shared__ __align__(16) float s_a[16][46];
    __shared__ int s_t[16];
    int nv = min(16, Etot - e0);
    for (int idx = j; idx < nv * EAK; idx += 128) {
        int t = idx / EAK, k = idx % EAK;
        s_a[t][k] = ea[(size_t)(e0 + t) * EAK + k];
    }
    if (j < 16) { s_a[j][45] = 0.0f; s_t[j] = (j < nv) ? et[e0 + j] : 0; }
    __syncthreads();
    u64 acc[16];
#pragma unroll
    for (int t = 0; t < 16; t++) acc[t] = 0ull;
    const u64* wp = (const u64*)&g_eWT[0][0];
#pragma unroll
    for (int p = 0; p < 23; p++) {
        u64 w = wp[p * 128 + j];
#pragma unroll
        for (int t = 0; t < 16; t++)
            acc[t] = fma2(*(const u64*)&s_a[t][2 * p], w, acc[t]);
    }
    float ebj = eb[j];
    for (int t = 0; t < nv; t++)
        g_e[(size_t)(e0 + t) * HIDN + j] =
            lemb[(size_t)s_t[t] * HIDN + j] + hadd2(acc[t]) + ebj;
}

// ---------------------------------------------------------------------------
// TENSOR node_pre: 64 nodes/CTA, 4 GEMMs -> g_np
#define NP_STR  132
#define NP_SMEM ((64 * NP_STR + IMG_ELEMS) * 4)
__global__ void __launch_bounds__(256, 2) k_node_pre_m(int l, int Ntot) {
    extern __shared__ float sm[];
    uint32_t* sA = (uint32_t*)sm;
    uint32_t* sB = (uint32_t*)sm + 64 * NP_STR;
    int tid = threadIdx.x, lane = tid & 31, w = tid >> 5;
    int RO = (w >> 1) * 16, CO = (w & 1) * 64;
    int n0 = blockIdx.x * 64;
    int nv = min(64, Ntot - n0);

    const float4* src = (const float4*)(g_x + (size_t)n0 * HIDN);
    for (int i = tid; i < 2048; i += 256) {
        int r = i >> 5, k = (i & 31) << 2;
        uint4 t4 = make_uint4(0u, 0u, 0u, 0u);
        if (r < nv) {
            float4 v = src[i];
            t4 = make_uint4(f2t(v.x), f2t(v.y), f2t(v.z), f2t(v.w));
        }
        *(uint4*)&sA[r * NP_STR + k] = t4;
    }

    int lr = lane >> 2, lc2 = (lane & 3) * 2;
    const int imgs[4] = { 10 + l, 13 + l, 16 + l, 19 + l };
#pragma unroll 1
    for (int blk = 0; blk < 4; blk++) {
        const uint4* ws = (const uint4*)&g_img[imgs[blk]][0];
        uint4* wd = (uint4*)sB;
        for (int i = tid; i < IMG_ELEMS / 4; i += 256) wd[i] = ws[i];
        __syncthreads();
        float acc[8][4];
        zacc(acc);
        gemm16(sA, NP_STR, 0, sB, RO, CO, lane, acc);
        int r0 = RO + lr, r1 = r0 + 8;
#pragma unroll
        for (int ct = 0; ct < 8; ct++) {
            int c = blk * 128 + CO + 8 * ct + lc2;
            if (r0 < nv) *(float2*)&g_np[(size_t)(n0 + r0) * 512 + c] =
                make_float2(acc[ct][0], acc[ct][1]);
            if (r1 < nv) *(float2*)&g_np[(size_t)(n0 + r1) * 512 + c] =
                make_float2(acc[ct][2], acc[ct][3]);
        }
        __syncthreads();
    }
}

// ---------------------------------------------------------------------------
// TENSOR edge layer: 64 edges/CTA, 3 CTAs/SM via half-width B streaming.
// smem floats: A 8448 | Bhalf 9216 | b1 128 | b2 128 | src 64 | dst 64
#define EL_A    0
#define EL_B    8448
#define EL_B1   (EL_B + 128 * SBH_STR)   // 17664
#define EL_B2   (EL_B1 + 128)
#define EL_SRC  (EL_B2 + 128)
#define EL_DST  (EL_SRC + 64)
#define EL_SMEM ((EL_DST + 64) * 4)      // 72192 B -> 3 CTAs/SM

// copy half h (64 cols) of image t into sB (stride 72)
__device__ __forceinline__ void copy_bhalf(uint32_t* sB, int t, int h, int tid) {
    const uint4* ws = (const uint4*)&g_img[t][0];
    uint4* wd = (uint4*)sB;
#pragma unroll 4
    for (int i = tid; i < 2048; i += 256) {
        int k = i >> 4, q = i & 15;
        wd[k * (SBH_STR / 4) + q] = ws[k * 34 + 16 * h + q];
    }
}

__global__ void __launch_bounds__(256, 3) k_edge_layer_m(
        const int* __restrict__ ei, const float* __restrict__ be,
        const float* __restrict__ bpre, int l, int Etot) {
    extern __shared__ float sm[];
    uint32_t* sA = (uint32_t*)(sm + EL_A);
    float*    fA = sm + EL_A;
    uint32_t* sB = (uint32_t*)(sm + EL_B);
    float* sb1 = sm + EL_B1;
    float* sb2 = sm + EL_B2;
    int* ssrc = (int*)(sm + EL_SRC);
    int* sdst = (int*)(sm + EL_DST);

    int tid = threadIdx.x, lane = tid & 31, w = tid >> 5;
    int RO = (w >> 1) * 16, CO32 = (w & 1) * 32;
    int e0 = blockIdx.x * 64;
    int nv = min(64, Etot - e0);

    if (tid < 128) { sb1[tid] = be[tid]; sb2[tid] = bpre[tid]; }
    else if (tid < 192) {
        int t = tid - 128, valid = t < nv;
        ssrc[t] = valid ? ei[e0 + t] : 0;
        sdst[t] = valid ? ei[Etot + e0 + t] : 0;
    }
    {
        const float4* src = (const float4*)(g_e + (size_t)e0 * HIDN);
        for (int i = tid; i < 2048; i += 256) {
            int r = i >> 5, k = (i & 31) << 2;
            uint4 t4 = make_uint4(0u, 0u, 0u, 0u);
            if (r < nv) {
                float4 v = src[i];
                t4 = make_uint4(f2t(v.x), f2t(v.y), f2t(v.z), f2t(v.w));
            }
            *(uint4*)&sA[r * 132 + k] = t4;
        }
    }

    int k0 = lane * 4;
    float accA[4][4], accB[4][4];

    // ============ phase 1: e' = silu(e@WeE + be + a1[src] + a2[dst]) =======
    copy_bhalf(sB, l, 0, tid);
    __syncthreads();
    zacc4(accA);
    gemm_h(sA, sB, RO, CO32, lane, accA);
    __syncthreads();
    copy_bhalf(sB, l, 1, tid);
    __syncthreads();
    zacc4(accB);
    gemm_h(sA, sB, RO, CO32, lane, accB);
    __syncthreads();                     // all sA reads done

    stage_h(fA, RO, CO32,      lane, accA);   // cols [CO32, CO32+32)
    stage_h(fA, RO, 64 + CO32, lane, accB);   // cols [64+CO32, ...)
    __syncthreads();

    // epilogue 1 (row-per-warp, in-place in sA)
    {
        float4 bb = *(const float4*)(sb1 + k0);
#pragma unroll 2
        for (int rr = 0; rr < 8; rr++) {
            int r = w * 8 + rr;
            int sn = ssrc[r], dn = sdst[r];
            float4 a = *(const float4*)(fA + r * 132 + k0);
            float4 p = *(const float4*)(g_np + (size_t)sn * 512 + k0);
            float4 q = *(const float4*)(g_np + (size_t)dn * 512 + 128 + k0);
            float v0 = siluf(a.x + bb.x + p.x + q.x);
            float v1 = siluf(a.y + bb.y + p.y + q.y);
            float v2 = siluf(a.z + bb.z + p.z + q.z);
            float v3 = siluf(a.w + bb.w + p.w + q.w);
            if (r < nv)
                *(float4*)(g_e + (size_t)(e0 + r) * HIDN + k0) =
                    make_float4(v0, v1, v2, v3);
            *(uint4*)(sA + r * 132 + k0) =
                make_uint4(f2t(v0), f2t(v1), f2t(v2), f2t(v3));
        }
    }
    __syncthreads();

    // ============ phase 2: m = silu(e'@WpE + bpre + p1[src] + p2[dst]) =====
    copy_bhalf(sB, 3 + l, 0, tid);
    __syncthreads();
    zacc4(accA);
    gemm_h(sA, sB, RO, CO32, lane, accA);
    __syncthreads();
    copy_bhalf(sB, 3 + l, 1, tid);
    __syncthreads();
    zacc4(accB);
    gemm_h(sA, sB, RO, CO32, lane, accB);
    __syncthreads();

    stage_h(fA, RO, CO32,      lane, accA);
    stage_h(fA, RO, 64 + CO32, lane, accB);
    __syncthreads();

    // epilogue 2 (row-per-warp): agg[dst] += m
    {
        float4 bb = *(const float4*)(sb2 + k0);
#pragma unroll 2
        for (int rr = 0; rr < 8; rr++) {
            int r = w * 8 + rr;
            if (r >= nv) break;
            int sn = ssrc[r], dn = sdst[r];
            float4 a = *(const float4*)(fA + r * 132 + k0);
            float4 p = *(const float4*)(g_np + (size_t)sn * 512 + 256 + k0);
            float4 q = *(const float4*)(g_np + (size_t)dn * 512 + 384 + k0);
            float m0 = siluf(a.x + bb.x + p.x + q.x);
            float m1 = siluf(a.y + bb.y + p.y + q.y);
            float m2 = siluf(a.z + bb.z + p.z + q.z);
            float m3 = siluf(a.w + bb.w + p.w + q.w);
            asm volatile("red.add.v4.f32 [%0], {%1, %2, %3, %4};"
                         :: "l"(g_agg + (size_t)dn * HIDN + k0),
                            "f"(m0), "f"(m1), "f"(m2), "f"(m3) : "memory");
        }
    }
}

// ---------------------------------------------------------------------------
// TENSOR node_post: 32 nodes/CTA, 128 threads; K=256 via 2 accumulating chunks
#define PO_STR  264
#define PO_B    (32 * PO_STR)            // 8448
#define PO_BIA  (PO_B + IMG_ELEMS)       // 25856
#define PO_INV  (PO_BIA + 128)
#define PO_SMEM ((PO_INV + 32) * 4)
__global__ void __launch_bounds__(128, 2) k_node_post_m(
        const float* __restrict__ bpost, int l, int do_silu, int Ntot) {
    extern __shared__ float sm[];
    uint32_t* sA = (uint32_t*)sm;
    uint32_t* sB = (uint32_t*)sm + PO_B;
    float* sbias = sm + PO_BIA;
    float* sinv  = sm + PO_INV;

    int tid = threadIdx.x, lane = tid & 31, w = tid >> 5;
    int RO = (w >> 1) * 16, CO = (w & 1) * 64;
    int n0 = blockIdx.x * 32;
    int nv = min(32, Ntot - n0);

    if (tid < 128) sbias[tid] = bpost[tid];
    if (tid < 32) sinv[tid] = (tid < nv) ? 1.0f / fmaxf(g_deg[n0 + tid], 1.0f) : 0.0f;
    __syncthreads();

    for (int i = tid; i < 2048; i += 128) {
        int r = i >> 6, k = (i & 63) << 2;
        uint4 t4 = make_uint4(0u, 0u, 0u, 0u);
        if (r < nv) {
            if (k < 128) {
                float4 v = *(const float4*)(g_x + (size_t)(n0 + r) * HIDN + k);
                t4 = make_uint4(f2t(v.x), f2t(v.y), f2t(v.z), f2t(v.w));
            } else {
                float inv = sinv[r];
                float* ap = g_agg + (size_t)(n0 + r) * HIDN + (k - 128);
                float4 v = *(const float4*)ap;
                t4 = make_uint4(f2t(v.x * inv), f2t(v.y * inv), f2t(v.z * inv), f2t(v.w * inv));
                *(float4*)ap = make_float4(0.f, 0.f, 0.f, 0.f);  // re-zero for next layer
            }
        }
        *(uint4*)&sA[r * PO_STR + k] = t4;
    }

    float acc[8][4];
    zacc(acc);
#pragma unroll 1
    for (int cchunk = 0; cchunk < 2; cchunk++) {
        const uint4* ws = (const uint4*)&g_img[22 + 2 * l + cchunk][0];
        uint4* wd = (uint4*)sB;
        for (int i = tid; i < IMG_ELEMS / 4; i += 128) wd[i] = ws[i];
        __syncthreads();
        gemm16(sA, PO_STR, cchunk * 128, sB, RO, CO, lane, acc);
        __syncthreads();
    }

    int lr = lane >> 2, lc2 = (lane & 3) * 2;
    int r0 = RO + lr, r1 = r0 + 8;
#pragma unroll
    for (int ct = 0; ct < 8; ct++) {
        int c = CO + 8 * ct + lc2;
        float b0v = sbias[c], b1v = sbias[c + 1];
        float v00 = acc[ct][0] + b0v, v01 = acc[ct][1] + b1v;
        float v10 = acc[ct][2] + b0v, v11 = acc[ct][3] + b1v;
        if (do_silu) { v00 = siluf(v00); v01 = siluf(v01); v10 = siluf(v10); v11 = siluf(v11); }
        if (r0 < nv) *(float2*)&g_x[(size_t)(n0 + r0) * HIDN + c] = make_float2(v00, v01);
        if (r1 < nv) *(float2*)&g_x[(size_t)(n0 + r1) * HIDN + c] = make_float2(v10, v11);
    }
}

__global__ void k_copy_x(float* __restrict__ out, int Ntot) {
    int i = blockIdx.x * blockDim.x + threadIdx.x;
    if (i < Ntot * HIDN) out[i] = g_x[i];
}

// ---------------------------------------------------------------------------
// TENSOR readout: 64 edges/CTA, row-major staged epilogues
#define RD_A    0
#define RD_B    (64 * 132)
#define RD_B1   (RD_B + IMG_ELEMS)       // 25856
#define RD_B2   (RD_B1 + 128)
#define RD_RES  (RD_B2 + 384)
#define RD_SMEM ((RD_RES + 64 * 12) * 4)

__global__ void __launch_bounds__(256, 2) k_readout_m(
        const float* __restrict__ ea, const float* __restrict__ b1,
        const float* __restrict__ b2, float* __restrict__ out, int Etot) {
    extern __shared__ float sm[];
    uint32_t* sA = (uint32_t*)(sm + RD_A);
    uint32_t* sB = (uint32_t*)(sm + RD_B);
    float*    fB = sm + RD_B;            // staging view of sB
    float* sb1 = sm + RD_B1;
    float* sb2 = sm + RD_B2;
    float* sres = sm + RD_RES;      // [64 rows][12] (9 used)

    int tid = threadIdx.x, lane = tid & 31, w = tid >> 5;
    int RO = (w >> 1) * 16, CO = (w & 1) * 64;
    int e0 = blockIdx.x * 64;
    int nv = min(64, Etot - e0);

    if (tid < 128) sb1[tid] = b1[tid];
    for (int i = tid; i < 384; i += 256) sb2[i] = (i < OUTK) ? b2[i] : 0.0f;
    for (int i = tid; i < 64 * 9; i += 256) {
        int r = i / 9, m = i % 9;
        sres[r * 12 + m] = (r < nv) ? ea[(size_t)(e0 + r) * EAK + m * 5 + 4] : 0.0f;
    }
    {
        const float4* src = (const float4*)(g_e + (size_t)e0 * HIDN);
        for (int i = tid; i < 2048; i += 256) {
            int r = i >> 5, k = (i & 31) << 2;
            uint4 t4 = make_uint4(0u, 0u, 0u, 0u);
            if (r < nv) {
                float4 v = src[i];
                t4 = make_uint4(f2t(v.x), f2t(v.y), f2t(v.z), f2t(v.w));
            }
            *(uint4*)&sA[r * 132 + k] = t4;
        }
        const uint4* ws = (const uint4*)&g_img[6][0];
        uint4* wd = (uint4*)sB;
        for (int i = tid; i < IMG_ELEMS / 4; i += 256) wd[i] = ws[i];
    }
    __syncthreads();

    float acc[8][4];
    zacc(acc);
    gemm16(sA, 132, 0, sB, RO, CO, lane, acc);
    __syncthreads();                     // done reading sA & sB

    stage_acc(fB, 132, RO, CO, lane, acc);
    __syncthreads();

    // h = silu(D + b1) -> sA (tf32), row-per-warp
    int k0 = lane * 4;
    {
        float4 bb = *(const float4*)(sb1 + k0);
#pragma unroll 2
        for (int rr = 0; rr < 8; rr++) {
            int r = w * 8 + rr;
            float4 a = *(const float4*)(fB + r * 132 + k0);
            *(uint4*)(sA + r * 132 + k0) = make_uint4(
                f2t(siluf(a.x + bb.x)), f2t(siluf(a.y + bb.y)),
                f2t(siluf(a.z + bb.z)), f2t(siluf(a.w + bb.w)));
        }
    }
    __syncthreads();

#pragma unroll 1
    for (int cc = 0; cc < 3; cc++) {
        const uint4* ws = (const uint4*)&g_img[7 + cc][0];
        uint4* wd = (uint4*)sB;
        for (int i = tid; i < IMG_ELEMS / 4; i += 256) wd[i] = ws[i];
        __syncthreads();
        zacc(acc);
        gemm16(sA, 132, 0, sB, RO, CO, lane, acc);
        __syncthreads();                 // done reading sB (and sA)

        stage_acc(fB, 132, RO, CO, lane, acc);
        __syncthreads();

        int o = cc * 128 + k0;
        if (o < OUTK) {                  // 4-block never straddles 40-boundary
            int mf = o / 40;
            float4 bb = *(const float4*)(sb2 + o);
#pragma unroll 2
            for (int rr = 0; rr < 8; rr++) {
                int r = w * 8 + rr;
                if (r >= nv) break;
                float4 a = *(const float4*)(fB + r * 132 + k0);
                float rv = sres[r * 12 + mf];
                *(float4*)(out + (size_t)(e0 + r) * OUTK + o) =
                    make_float4(a.x + bb.x + rv, a.y + bb.y + rv,
                                a.z + bb.z + rv, a.w + bb.w + rv);
            }
        }
        __syncthreads();                 // staging reads done before next copy
    }
}

// ===========================================================================
extern "C" void kernel_launch(void* const* d_in, const int* in_sizes, int n_in,
                              void* d_out, int out_size) {
    const float* edge_attr   = (const float*)d_in[0];
    const int*   edge_type   = (const int*)  d_in[1];
    const float* pos         = (const float*)d_in[2];
    const int*   pos_w       = (const int*)  d_in[3];
    const int*   edge_index  = (const int*)  d_in[4];
    const float* layer_embed = (const float*)d_in[5];
    const float* wte         = (const float*)d_in[6];
    const float* node_W      = (const float*)d_in[7];
    const float* node_b      = (const float*)d_in[8];
    const float* edge_W      = (const float*)d_in[9];
    const float* edge_b      = (const float*)d_in[10];
    const float* gnn_We      = (const float*)d_in[11];
    const float* gnn_be      = (const float*)d_in[12];
    const float* gnn_Wpre    = (const float*)d_in[13];
    const float* gnn_bpre    = (const float*)d_in[14];
    const float* gnn_Wpost   = (const float*)d_in[15];
    const float* gnn_bpost   = (const float*)d_in[16];
    const float* out_W1      = (const float*)d_in[17];
    const float* out_b1      = (const float*)d_in[18];
    const float* out_W2      = (const float*)d_in[19];
    const float* out_b2      = (const float*)d_in[20];

    int E = in_sizes[1];
    int N = in_sizes[3];
    if (E > EE) E = EE;
    if (N > NN) N = NN;

    float* outp = (float*)d_out;
    float* out_x = nullptr; float* out_o = nullptr;
    long xsz = (long)N * HIDN, osz = (long)E * OUTK;
    if ((long)out_size >= xsz + osz)      { out_x = outp; out_o = outp + xsz; }
    else if ((long)out_size == osz)       { out_o = outp; }
    else                                  { out_x = outp; }

    cudaFuncSetAttribute(k_edge_layer_m, cudaFuncAttributeMaxDynamicSharedMemorySize, EL_SMEM);
    cudaFuncSetAttribute(k_readout_m,    cudaFuncAttributeMaxDynamicSharedMemorySize, RD_SMEM);
    cudaFuncSetAttribute(k_node_pre_m,   cudaFuncAttributeMaxDynamicSharedMemorySize, NP_SMEM);
    cudaFuncSetAttribute(k_node_post_m,  cudaFuncAttributeMaxDynamicSharedMemorySize, PO_SMEM);

    int EB16 = (E + 15) / 16;
    int EB64 = (E + 63) / 64, NB64 = (N + 63) / 64, NB32 = (N + 31) / 32;
    int packN = 2944 + N_IMG * IMG_ELEMS + N;

    k_pack_all<<<(packN + 255) / 256, 256>>>(gnn_We, gnn_Wpre, gnn_Wpost,
                                             out_W1, out_W2, edge_W, N);          // 1
    k_init_fused<<<N + EB16, 128>>>(pos, pos_w, wte, node_W, node_b,
                                    edge_attr, edge_type, layer_embed, edge_b,
                                    N, E);                                        // 2
    k_node_pre_m<<<NB64, 256, NP_SMEM>>>(0, N);                                   // 3
    k_edge_layer_m<<<EB64, 256, EL_SMEM>>>(edge_index, gnn_be, gnn_bpre, 0, E);   // 4 (profiled)
    k_count_deg<<<(E + 255) / 256, 256>>>(edge_index, E);                         // 5
    k_node_post_m<<<NB32, 128, PO_SMEM>>>(gnn_bpost, 0, 1, N);                    // 6

    for (int l = 1; l < NL; l++) {
        k_node_pre_m<<<NB64, 256, NP_SMEM>>>(l, N);
        k_edge_layer_m<<<EB64, 256, EL_SMEM>>>(edge_index,
                                               gnn_be + l * HIDN,
                                               gnn_bpre + l * HIDN, l, E);
        k_node_post_m<<<NB32, 128, PO_SMEM>>>(gnn_bpost + l * HIDN, l,
                                              (l < NL - 1) ? 1 : 0, N);
    }

    if (out_x) k_copy_x<<<((long)N * HIDN + 255) / 256, 256>>>(out_x, N);
    if (out_o) k_readout_m<<<EB64, 256, RD_SMEM>>>(edge_attr, out_b1, out_b2, out_o, E);
}